// round 6
// baseline (speedup 1.0000x reference)
#include <cuda_runtime.h>

#define NTHREADS 224
#define BLOCKS_PER_SM 4
#define NBLOCKS  (148 * BLOCKS_PER_SM)   // persistent grid

struct PS { int base; float w0, w1; };   // w0 = ap*(1-b1), w1 = ap*b1

// Per-plane sampling params for one lane (sub-lane s, column p = s>>1).
__device__ __forceinline__ PS plane_setup(float u, float v, int s, int p)
{
    // x = ((u+1)*512 - 1)*0.5 == u*256 + 255.5 (<=1 ulp; bilinear is continuous)
    float x = fmaf(u, 256.0f, 255.5f);
    float y = fmaf(v, 256.0f, 255.5f);
    x = fminf(fmaxf(x, 0.0f), 511.0f);
    y = fminf(fmaxf(y, 0.0f), 511.0f);

    float x0f = floorf(x);
    float y0f = floorf(y);
    float xbf = fminf(x0f, 510.0f);
    float ybf = fminf(y0f, 510.0f);

    // a1 = weight of column xb+1. Normally wx; when x==511 exactly, a1 = 511-510 = 1,
    // which is exactly the border-clamped result (all weight on column 511).
    float a1 = x - xbf;
    float b1 = y - ybf;
    float ap = p ? a1 : (1.0f - a1);

    PS ps;
    ps.w0 = ap * (1.0f - b1);
    ps.w1 = ap * b1;
    ps.base = ((((int)ybf << 9) + (int)xbf) << 1) + s;  // float4 idx; slots [x0h0 x0h1 x1h0 x1h1]
    return ps;
}

__global__ void __launch_bounds__(NTHREADS, BLOCKS_PER_SM)
geo_encoder_kernel(
    const float*  __restrict__ coords,   // [N,3]
    const float4* __restrict__ pxy,
    const float4* __restrict__ pxz,
    const float4* __restrict__ pyz,
    const float*  __restrict__ Wp,       // [8,24]
    const float*  __restrict__ bp,       // [8]
    float*        __restrict__ out,      // [N,8]
    int n)
{
    const int t   = threadIdx.x;
    const int s   = t & 3;       // sub-lane in quad
    const int h   = s & 1;       // rank half (float4 within texel) this lane loads
    const int p   = s >> 1;      // x-column this lane loads; also output group
    const int grp = p;

    // W slice in registers: Wreg[j*12 + q*4 + r] = W[4*grp+j][q*8 + h*4 + r]
    float Wreg[48];
    float bias[4];
    const int row0 = 4 * grp;
    #pragma unroll
    for (int j = 0; j < 4; j++) {
        bias[j] = __ldg(bp + row0 + j);
        #pragma unroll
        for (int q = 0; q < 3; q++)
            #pragma unroll
            for (int r = 0; r < 4; r++)
                Wreg[j * 12 + q * 4 + r] = __ldg(Wp + (row0 + j) * 24 + q * 8 + h * 4 + r);
    }

    const int quad   = (blockIdx.x * NTHREADS + t) >> 2;
    const int nquads = (NBLOCKS * NTHREADS) >> 2;
    const int niter  = (n + nquads - 1) / nquads;   // uniform across lanes

    for (int k = 0; k < niter; k++) {
        const int  i   = quad + k * nquads;
        const bool act = (i < n);
        const int  ie  = act ? i : 0;

        float cx = __ldg(coords + 3 * ie + 0);
        float cy = __ldg(coords + 3 * ie + 1);
        float cz = __ldg(coords + 3 * ie + 2);
        cx = fminf(fmaxf(cx, -1.0f), 1.0f);
        cy = fminf(fmaxf(cy, -1.0f), 1.0f);
        cz = fminf(fmaxf(cz, -1.0f), 1.0f);

        const PS a = plane_setup(cx, cy, s, p);
        const PS b = plane_setup(cx, cz, s, p);
        const PS c = plane_setup(cy, cz, s, p);

        // 6 independent gathers, front-batched (max MLP). +1024 float4 = next row.
        const float4 ta = __ldg(pxy + a.base);
        const float4 ba = __ldg(pxy + a.base + 1024);
        const float4 tb = __ldg(pxz + b.base);
        const float4 bb = __ldg(pxz + b.base + 1024);
        const float4 tc = __ldg(pyz + c.base);
        const float4 bc = __ldg(pyz + c.base + 1024);

        // partial features (this lane's column & half), 12 values
        float pf[12];
        pf[0]  = a.w0 * ta.x + a.w1 * ba.x;
        pf[1]  = a.w0 * ta.y + a.w1 * ba.y;
        pf[2]  = a.w0 * ta.z + a.w1 * ba.z;
        pf[3]  = a.w0 * ta.w + a.w1 * ba.w;
        pf[4]  = b.w0 * tb.x + b.w1 * bb.x;
        pf[5]  = b.w0 * tb.y + b.w1 * bb.y;
        pf[6]  = b.w0 * tb.z + b.w1 * bb.z;
        pf[7]  = b.w0 * tb.w + b.w1 * bb.w;
        pf[8]  = c.w0 * tc.x + c.w1 * bc.x;
        pf[9]  = c.w0 * tc.y + c.w1 * bc.y;
        pf[10] = c.w0 * tc.z + c.w1 * bc.z;
        pf[11] = c.w0 * tc.w + c.w1 * bc.w;

        // fused feature-reduce (over x-columns, xor bit1) + register matvec
        float o0 = 0.f, o1 = 0.f, o2 = 0.f, o3 = 0.f;
        #pragma unroll
        for (int q = 0; q < 12; q++) {
            const float g = pf[q] + __shfl_xor_sync(0xffffffffu, pf[q], 2);
            o0 += Wreg[q]      * g;
            o1 += Wreg[12 + q] * g;
            o2 += Wreg[24 + q] * g;
            o3 += Wreg[36 + q] * g;
        }

        // combine rank halves (xor bit0)
        o0 += __shfl_xor_sync(0xffffffffu, o0, 1);
        o1 += __shfl_xor_sync(0xffffffffu, o1, 1);
        o2 += __shfl_xor_sync(0xffffffffu, o2, 1);
        o3 += __shfl_xor_sync(0xffffffffu, o3, 1);

        if (act && h == 0) {
            float4 v;
            v.x = fminf(fmaxf(o0 + bias[0], -10.0f), 10.0f);
            v.y = fminf(fmaxf(o1 + bias[1], -10.0f), 10.0f);
            v.z = fminf(fmaxf(o2 + bias[2], -10.0f), 10.0f);
            v.w = fminf(fmaxf(o3 + bias[3], -10.0f), 10.0f);
            reinterpret_cast<float4*>(out)[(i << 1) + grp] = v;
        }
    }
}

extern "C" void kernel_launch(void* const* d_in, const int* in_sizes, int n_in,
                              void* d_out, int out_size)
{
    const float*  coords = (const float*)d_in[0];
    const float4* pxy    = (const float4*)d_in[1];
    const float4* pxz    = (const float4*)d_in[2];
    const float4* pyz    = (const float4*)d_in[3];
    const float*  Wp     = (const float*)d_in[4];
    const float*  bp     = (const float*)d_in[5];
    float*        out    = (float*)d_out;

    const int n = in_sizes[0] / 3;
    geo_encoder_kernel<<<NBLOCKS, NTHREADS>>>(coords, pxy, pxz, pyz, Wp, bp, out, n);
}